// round 4
// baseline (speedup 1.0000x reference)
#include <cuda_runtime.h>

#define BB 64
#define TT 8000
#define SS 10
#define CHUNKS 11
#define ROWSPC ((TT + CHUNKS - 1) / CHUNKS)   // 728
#define NACC 110                              // 100 sel + 10 tot
#define FULL 0xFFFFFFFFu
#define FLT_MAX_C 3.402823466e+38f
#define LN2F 0.6931471805599453f

// Scratch (no allocations allowed). Zero-initialized device globals.
__device__ float    g_part[BB * CHUNKS * NACC];
__device__ double   g_bsum[BB];
__device__ unsigned g_bticket[BB];
__device__ unsigned g_ticket2;

__device__ __forceinline__ unsigned enc_f32(float x) {
    unsigned b = __float_as_uint(x);
    return (b & 0x80000000u) ? ~b : (b | 0x80000000u);
}
__device__ __forceinline__ float dec_f32(unsigned e) {
    unsigned b = (e & 0x80000000u) ? (e & 0x7FFFFFFFu) : ~e;
    return __uint_as_float(b);
}

// Per-class pairwise body: accumulates in LG2 units (scaled by ln2 at combine).
template <int IH, int JH>
__device__ __forceinline__ void pw_body(const float* __restrict__ pred,
                                        const float* __restrict__ tgt,
                                        int b, int t0, int tend, int slot,
                                        float sel[5][5], float tot[5]) {
    for (int t = t0 + slot; t < tend; t += 64) {
        const size_t base = ((size_t)b * TT + (size_t)t) * SS;
        // 6-element windows: elements [IH*4, IH*4+6) cover [IH*5, IH*5+5).
        const float2* pp = reinterpret_cast<const float2*>(pred + base + IH * 4);
        const float2* tp = reinterpret_cast<const float2*>(tgt  + base + JH * 4);
        const float2 p0 = pp[0], p1 = pp[1], p2 = pp[2];
        const float2 q0 = tp[0], q1 = tp[1], q2 = tp[2];
        const float pe[6] = {p0.x, p0.y, p1.x, p1.y, p2.x, p2.y};
        const float te[6] = {q0.x, q0.y, q1.x, q1.y, q2.x, q2.y};

        float diff[5];
#pragma unroll
        for (int ii = 0; ii < 5; ii++) {
            const float p  = pe[ii + IH];          // static index
            const float l1 = __log2f(p);           // lg2(p)       (1 MUFU)
            const float l2 = __log2f(1.0f - p);    // lg2(1-p)     (1 MUFU)
            diff[ii] = l1 - l2;
            tot[ii] += l2;
        }
#pragma unroll
        for (int jj = 0; jj < 5; jj++) {
            const float tj = te[jj + JH];          // exactly 0.0f or 1.0f
#pragma unroll
            for (int ii = 0; ii < 5; ii++)
                sel[ii][jj] = fmaf(diff[ii], tj, sel[ii][jj]);
        }
    }
}

// ---------------------------------------------------------------------------
// Single fused kernel: pairwise partials + (last chunk-block per batch) the
// warp-per-batch Hungarian + (last batch overall) the final mean.
// ---------------------------------------------------------------------------
__global__ __launch_bounds__(256, 5) void fused_kernel(const float* __restrict__ pred,
                                                       const float* __restrict__ tgt,
                                                       float* __restrict__ out) {
    __shared__ float s[8][30];
    __shared__ float s_cost[100];
    __shared__ float sv[SS + 1];

    const int b    = blockIdx.x / CHUNKS;
    const int c    = blockIdx.x % CHUNKS;
    const int tid  = threadIdx.x;
    const int w    = tid >> 5;
    const int lane = tid & 31;
    const int slot = tid & 63;
    const int q    = w >> 1;                  // warp-uniform class: ihalf=q&1, jhalf=q>>1

    const int t0   = c * ROWSPC;
    const int tend = (t0 + ROWSPC < TT) ? (t0 + ROWSPC) : TT;

    // ---- Phase 1: pairwise partial reduction (all 8 warps) ----
    {
        float sel[5][5];
        float tot[5];
#pragma unroll
        for (int ii = 0; ii < 5; ii++) {
            tot[ii] = 0.0f;
#pragma unroll
            for (int jj = 0; jj < 5; jj++) sel[ii][jj] = 0.0f;
        }

        switch (q) {
            case 0: pw_body<0, 0>(pred, tgt, b, t0, tend, slot, sel, tot); break;
            case 1: pw_body<1, 0>(pred, tgt, b, t0, tend, slot, sel, tot); break;
            case 2: pw_body<0, 1>(pred, tgt, b, t0, tend, slot, sel, tot); break;
            default: pw_body<1, 1>(pred, tgt, b, t0, tend, slot, sel, tot); break;
        }

        // Full-warp tree reduction of the 30 accumulators -> lane 0.
#pragma unroll
        for (int ii = 0; ii < 5; ii++) {
#pragma unroll
            for (int jj = 0; jj < 5; jj++) {
                float v = sel[ii][jj];
#pragma unroll
                for (int o = 16; o; o >>= 1) v += __shfl_down_sync(FULL, v, o);
                sel[ii][jj] = v;
            }
            float v = tot[ii];
#pragma unroll
            for (int o = 16; o; o >>= 1) v += __shfl_down_sync(FULL, v, o);
            tot[ii] = v;
        }

        if (lane == 0) {
#pragma unroll
            for (int ii = 0; ii < 5; ii++) {
#pragma unroll
                for (int jj = 0; jj < 5; jj++) s[w][ii * 5 + jj] = sel[ii][jj];
                s[w][25 + ii] = tot[ii];
            }
        }
        __syncthreads();

        if (tid < NACC) {
            int qq, idx;
            if (tid < 100) {
                const int i = tid / 10, j = tid % 10;
                const int ih = (i >= 5), jh = (j >= 5);
                qq  = jh * 2 + ih;
                idx = (i % 5) * 5 + (j % 5);
            } else {
                const int i = tid - 100;
                const int ih = (i >= 5);
                qq  = ih;                  // tot kept only by jhalf==0 classes
                idx = 25 + (i % 5);
            }
            // scale LG2-units -> natural log here, once
            g_part[(b * CHUNKS + c) * NACC + tid] =
                (s[2 * qq][idx] + s[2 * qq + 1][idx]) * LN2F;
        }
    }

    // ---- Ticket: last chunk-block of batch b proceeds (warp 0 only) ----
    __threadfence();
    __shared__ unsigned s_tkt;
    if (tid == 0) s_tkt = atomicAdd(&g_bticket[b], 1u);
    __syncthreads();
    if (w != 0) return;
    if (s_tkt != CHUNKS - 1) return;
    if (lane == 0) g_bticket[b] = 0;       // reset for graph replay (sole reader)
    __threadfence();

    // ---- Phase 2: Hungarian for batch b (one warp) ----
    for (int k = lane; k < 100; k += 32) {
        const int i = k / 10;
        float sl = 0.0f, to = 0.0f;
#pragma unroll
        for (int cc = 0; cc < CHUNKS; cc++) {
            const float* gp = &g_part[(b * CHUNKS + cc) * NACC];
            sl += __ldcg(&gp[k]);
            to += __ldcg(&gp[100 + i]);
        }
        s_cost[k] = -(to + sl) * (1.0f / (float)TT);
    }
    __syncwarp();

    const int cl = (lane >= 1 && lane <= SS) ? (lane - 1) : 0;  // safe smem column

    // JV warm start: v[j] = min_i cost[i][j]; u[i] = min_j (cost[i][j] - v[j]).
    float v = 0.0f, u = 0.0f;
    if (lane >= 1 && lane <= SS) {
        float mn = s_cost[cl];
#pragma unroll
        for (int i = 1; i < SS; i++) mn = fminf(mn, s_cost[i * 10 + cl]);
        v = mn;
        sv[lane] = mn;
    }
    __syncwarp();
    if (lane >= 1 && lane <= SS) {
        float mn = s_cost[cl * 10 + 0] - sv[1];
#pragma unroll
        for (int j = 1; j < SS; j++) mn = fminf(mn, s_cost[cl * 10 + j] - sv[j + 1]);
        u = mn;
    }

    int   p = 0, way = 0;   // lane j: assigned row of column j / alternating path
    float minv, upj;

    for (int root = 1; root <= SS; root++) {
        if (lane == 0) p = root;
        upj  = __shfl_sync(FULL, u, p & 31);     // u[p[j]] (unused where p==0)
        minv = FLT_MAX_C;
        unsigned used = 0u, rowm = 0u;
        int   j0 = 0;
        int   i0 = root;
        float u0 = __shfl_sync(FULL, u, root);

        while (true) {
            used |= 1u << j0;
            rowm |= 1u << i0;

            const bool  active = (lane >= 1) && (lane <= SS) && !((used >> lane) & 1u);
            const float cur    = s_cost[(i0 - 1) * 10 + cl] - u0 - v;
            if (active && cur < minv) { minv = cur; way = j0; }

            const unsigned key = active ? enc_f32(minv) : 0xFFFFFFFFu;
            const unsigned m   = __reduce_min_sync(FULL, key);
            const float delta  = dec_f32(m);                     // ALU decode, no shfl
            const unsigned bal = __ballot_sync(FULL, key == m);
            const int      j1  = __ffs(bal) - 1;                 // lowest j tie-break
            const int   pn     = __shfl_sync(FULL, p, j1);       // next i0 (0 = free)
            const float u0n    = __shfl_sync(FULL, upj, j1);     // u[pn]

            if (lane <= SS) {
                if ((used >> lane) & 1u) v -= delta;
                else                     minv -= delta;
            }
            if ((used >> lane) & 1u) upj += delta;
            if ((rowm >> lane) & 1u) u   += delta;

            j0 = j1; i0 = pn; u0 = u0n;
            if (pn == 0) break;
        }

        // Augment along the alternating path.
        while (j0) {
            const int jprev = __shfl_sync(FULL, way, j0);
            const int pprev = __shfl_sync(FULL, p, jprev);
            if (lane == j0) p = pprev;
            j0 = jprev;
        }
    }

    // Matched sum for this batch (exact f32 cost entries, f64 accumulate).
    double val = 0.0;
    if (lane >= 1 && lane <= SS) val = (double)s_cost[(p - 1) * 10 + cl];
#pragma unroll
    for (int o = 16; o; o >>= 1) val += __shfl_down_sync(FULL, val, o);
    if (lane == 0) g_bsum[b] = val;

    // ---- Phase 3: last batch overall reduces the mean ----
    __threadfence();
    unsigned t2 = 0;
    if (lane == 0) t2 = atomicAdd(&g_ticket2, 1u);
    t2 = __shfl_sync(FULL, t2, 0);
    if (t2 == BB - 1) {
        if (lane == 0) g_ticket2 = 0;              // reset for graph replay
        __threadfence();
        double x = __ldcg(&g_bsum[lane]) + __ldcg(&g_bsum[lane + 32]);
#pragma unroll
        for (int o = 16; o; o >>= 1) x += __shfl_down_sync(FULL, x, o);
        if (lane == 0) out[0] = (float)(x / (double)(BB * SS));
    }
}

extern "C" void kernel_launch(void* const* d_in, const int* in_sizes, int n_in,
                              void* d_out, int out_size) {
    const float* pred = (const float*)d_in[0];
    const float* tgt  = (const float*)d_in[1];
    fused_kernel<<<BB * CHUNKS, 256>>>(pred, tgt, (float*)d_out);
}